// round 4
// baseline (speedup 1.0000x reference)
#include <cuda_runtime.h>

#define TABLE_ROWS 1025
#define HIDDEN     128
#define SEQ        512
#define BATCH      2
#define MAXSEQ     512

// Scratch for the projected tables (allocation-free rule: device globals).
__device__ float g_Ass[TABLE_ROWS * HIDDEN];   // pe_ss @ W[:, :128]^T + bias
__device__ float g_Aee[TABLE_ROWS * HIDDEN];   // pe_ee @ W[:, 128:]^T

// Packed dual-FMA (Blackwell f32x2).
#define FFMA2(acc, a, b) \
    asm("fma.rn.f32x2 %0, %1, %2, %3;" : "=l"(acc) : "l"(a), "l"(b), "l"(acc))

// ---------------------------------------------------------------------------
// Kernel 1: project the 1025-row tables through the linear layer.
//   A_ss[t,h] = dot(pe_ss[t,:], W[h, 0:128])   + bias[h]
//   A_ee[t,h] = dot(pe_ee[t,:], W[h, 128:256])
// grid = (74, 2) = 148 blocks -> exactly one wave.
// block = 256 threads: h = tid&127, half = tid>>7. Each block does 14 table
// rows, split 7/7 between the halves -> short per-warp chains (448 FFMA2),
// 2 warps/SMSP to cover LDS/LDG latency.
// ---------------------------------------------------------------------------
#define ROWS_PER_BLOCK 14
#define ROWS_PER_HALF  7

__global__ void __launch_bounds__(256)
project_tables_kernel(const float* __restrict__ pe_ss,
                      const float* __restrict__ pe_ee,
                      const float* __restrict__ W,
                      const float* __restrict__ bias)
{
    const int sel  = blockIdx.y;           // 0 -> ss, 1 -> ee
    const int t0   = blockIdx.x * ROWS_PER_BLOCK;
    const int h    = threadIdx.x & 127;
    const int half = threadIdx.x >> 7;     // 0 or 1

    const float* __restrict__ pe = sel ? pe_ee : pe_ss;
    float* __restrict__ outA     = sel ? g_Aee : g_Ass;

    // 14 rows x 128 floats = 14 x 32 ulonglong2 (7 KB).
    __shared__ ulonglong2 pe_sm[ROWS_PER_BLOCK][32];

    const ulonglong2* __restrict__ peg = reinterpret_cast<const ulonglong2*>(pe);
    for (int lin = threadIdx.x; lin < ROWS_PER_BLOCK * 32; lin += 256) {
        const int r = lin >> 5;
        const int c = lin & 31;
        const int t = t0 + r;
        ulonglong2 v;
        if (t < TABLE_ROWS) v = peg[(size_t)t * 32 + c];
        else { v.x = 0ULL; v.y = 0ULL; }
        pe_sm[r][c] = v;
    }
    __syncthreads();

    unsigned long long acc[ROWS_PER_HALF];
    #pragma unroll
    for (int r = 0; r < ROWS_PER_HALF; r++) acc[r] = 0ULL;

    const int rbase = half * ROWS_PER_HALF;

    // W is [H, 2H] row-major; thread uses W[h, sel*128 : sel*128+128].
    const ulonglong2* __restrict__ W2 = reinterpret_cast<const ulonglong2*>(
        W + (size_t)h * (2 * HIDDEN) + sel * HIDDEN);

    #pragma unroll 8
    for (int kg = 0; kg < 32; kg++) {
        const ulonglong2 w = W2[kg];
        #pragma unroll
        for (int r = 0; r < ROWS_PER_HALF; r++) {
            const ulonglong2 p = pe_sm[rbase + r][kg];   // broadcast
            FFMA2(acc[r], w.x, p.x);
            FFMA2(acc[r], w.y, p.y);
        }
    }

    const float binit = sel ? 0.0f : bias[h];
    #pragma unroll
    for (int r = 0; r < ROWS_PER_HALF; r++) {
        const int t = t0 + rbase + r;
        if (t < TABLE_ROWS) {
            float lo, hi;
            asm("mov.b64 {%0, %1}, %2;" : "=f"(lo), "=f"(hi) : "l"(acc[r]));
            outA[(size_t)t * HIDDEN + h] = lo + hi + binit;
        }
    }
}

// ---------------------------------------------------------------------------
// Kernel 2: out[b,i,j,:] = relu(A_ss[ps[i]-ps[j]+512] + A_ee[pe[i]-pe[j]+512])
// grid = B*SEQ blocks (one per (b,i)), block = 256 threads = 8 warps.
// Each warp owns a CONTIGUOUS 64-j chunk. Positions are sorted -> ~37% of
// consecutive j share the same table index; the gather is predicated off
// (no branch, value kept in registers) when the index repeats.
// ---------------------------------------------------------------------------
__device__ __forceinline__ void ld_cond4(float4& v, const float4* p, int cond)
{
    asm volatile(
        "{\n\t.reg .pred q;\n\t"
        "setp.ne.s32 q, %4, 0;\n\t"
        "@q ld.global.nc.v4.f32 {%0, %1, %2, %3}, [%5];\n\t}"
        : "+f"(v.x), "+f"(v.y), "+f"(v.z), "+f"(v.w)
        : "r"(cond), "l"(p));
}

__global__ void __launch_bounds__(256)
fuse_gather_kernel(const int* __restrict__ pos_s,
                   const int* __restrict__ pos_e,
                   float* __restrict__ out)
{
    const int bi = blockIdx.x;          // b*SEQ + i
    const int b  = bi >> 9;
    const int i  = bi & (SEQ - 1);

    __shared__ int ps_sm[SEQ];
    __shared__ int pe_sm[SEQ];
    for (int j = threadIdx.x; j < SEQ; j += blockDim.x) {
        ps_sm[j] = pos_s[b * SEQ + j];
        pe_sm[j] = pos_e[b * SEQ + j];
    }
    __syncthreads();

    const int psi = ps_sm[i];
    const int pei = pe_sm[i];

    const int warp = threadIdx.x >> 5;
    const int lane = threadIdx.x & 31;

    const float4* __restrict__ Ass4 = reinterpret_cast<const float4*>(g_Ass);
    const float4* __restrict__ Aee4 = reinterpret_cast<const float4*>(g_Aee);
    float4* __restrict__ out4 =
        reinterpret_cast<float4*>(out + (size_t)bi * SEQ * HIDDEN) + lane;

    const int j0 = warp * 64;           // contiguous chunk per warp

    int prev_iss = -1, prev_iee = -1;   // indices are always >= 1
    float4 a = make_float4(0.f, 0.f, 0.f, 0.f);
    float4 e = make_float4(0.f, 0.f, 0.f, 0.f);

    #pragma unroll 4
    for (int jj = 0; jj < 64; jj++) {
        const int j   = j0 + jj;
        const int iss = psi - ps_sm[j] + MAXSEQ;   // warp-uniform, in [1,1023]
        const int iee = pei - pe_sm[j] + MAXSEQ;

        ld_cond4(a, Ass4 + iss * (HIDDEN / 4) + lane, iss - prev_iss);
        ld_cond4(e, Aee4 + iee * (HIDDEN / 4) + lane, iee - prev_iee);
        prev_iss = iss;
        prev_iee = iee;

        float4 r;
        r.x = fmaxf(a.x + e.x, 0.0f);
        r.y = fmaxf(a.y + e.y, 0.0f);
        r.z = fmaxf(a.z + e.z, 0.0f);
        r.w = fmaxf(a.w + e.w, 0.0f);

        out4[j * (HIDDEN / 4)] = r;
    }
}

// ---------------------------------------------------------------------------
// Inputs (metadata order): 0 pos_s [B,S] i32, 1 pos_e [B,S] i32,
// 2 pe_ss [1025,128] f32, 3 pe_se (unused), 4 pe_es (unused),
// 5 pe_ee [1025,128] f32, 6 W [128,256] f32, 7 b [128] f32.
// Output: [B,S,S,H] f32.
// ---------------------------------------------------------------------------
extern "C" void kernel_launch(void* const* d_in, const int* in_sizes, int n_in,
                              void* d_out, int out_size)
{
    const int*   pos_s = (const int*)d_in[0];
    const int*   pos_e = (const int*)d_in[1];
    const float* pe_ss = (const float*)d_in[2];
    const float* pe_ee = (const float*)d_in[5];
    const float* W     = (const float*)d_in[6];
    const float* bias  = (const float*)d_in[7];
    float*       out   = (float*)d_out;

    dim3 grid1((TABLE_ROWS + ROWS_PER_BLOCK - 1) / ROWS_PER_BLOCK, 2); // (74, 2)
    project_tables_kernel<<<grid1, 256>>>(pe_ss, pe_ee, W, bias);

    fuse_gather_kernel<<<BATCH * SEQ, 256>>>(pos_s, pos_e, out);
}

// round 5
// speedup vs baseline: 1.0915x; 1.0915x over previous
#include <cuda_runtime.h>

#define TABLE_ROWS 1025
#define HIDDEN     128
#define SEQ        512
#define BATCH      2
#define MAXSEQ     512
#define R_MAX      44      // max contiguous table rows cached per table per tile

// Scratch for the projected tables (allocation-free rule: device globals).
__device__ float g_Ass[TABLE_ROWS * HIDDEN];   // pe_ss @ W[:, :128]^T + bias
__device__ float g_Aee[TABLE_ROWS * HIDDEN];   // pe_ee @ W[:, 128:]^T

// ---------------------------------------------------------------------------
// Kernel 1 (exact R1 config — measured best): project the tables.
// grid = (129, 2), block = 128 (thread = output h), 8 rows per block.
// ---------------------------------------------------------------------------
__global__ void __launch_bounds__(128)
project_tables_kernel(const float* __restrict__ pe_ss,
                      const float* __restrict__ pe_ee,
                      const float* __restrict__ W,
                      const float* __restrict__ bias)
{
    const int sel = blockIdx.y;            // 0 -> ss, 1 -> ee
    const int t0  = blockIdx.x * 8;
    const int h   = threadIdx.x;           // 0..127

    const float* __restrict__ pe = sel ? pe_ee : pe_ss;
    float* __restrict__ outA     = sel ? g_Aee : g_Ass;

    __shared__ float pe_sm[8][HIDDEN];

    #pragma unroll
    for (int r = 0; r < 8; r++) {
        int t = t0 + r;
        pe_sm[r][h] = (t < TABLE_ROWS) ? pe[(size_t)t * HIDDEN + h] : 0.0f;
    }
    __syncthreads();

    float acc[8];
    const float binit = sel ? 0.0f : bias[h];
    #pragma unroll
    for (int r = 0; r < 8; r++) acc[r] = binit;

    const float4* __restrict__ W4 =
        reinterpret_cast<const float4*>(W + (size_t)h * (2 * HIDDEN) + sel * HIDDEN);

    #pragma unroll 8
    for (int kg = 0; kg < HIDDEN / 4; kg++) {
        const float4 w = W4[kg];
        #pragma unroll
        for (int r = 0; r < 8; r++) {
            const float4 p = reinterpret_cast<const float4*>(pe_sm[r])[kg]; // broadcast
            acc[r] += w.x * p.x + w.y * p.y + w.z * p.z + w.w * p.w;
        }
    }

    #pragma unroll
    for (int r = 0; r < 8; r++) {
        int t = t0 + r;
        if (t < TABLE_ROWS) outA[(size_t)t * HIDDEN + h] = acc[r];
    }
}

// ---------------------------------------------------------------------------
// Kernel 2 (tiled): out[b,i,j,:] = relu(A_ss[ps_i-ps_j+512] + A_ee[pe_i-pe_j+512])
// 16x16 (i,j) tiles. Positions are SORTED, so the table indices needed by a
// tile form a contiguous range (typ. ~33 rows). Bulk-copy that slice into
// SMEM once (coalesced), then serve all 256 pairs from SMEM. Tiles whose
// range exceeds R_MAX fall back to direct __ldg (rare; correct either way).
// grid = (32, 32, 2) = 2048 blocks, 256 threads = 8 warps, 32 pairs/warp.
// ---------------------------------------------------------------------------
__global__ void __launch_bounds__(256)
fuse_gather_tiled(const int* __restrict__ pos_s,
                  const int* __restrict__ pos_e,
                  float* __restrict__ out)
{
    const int b  = blockIdx.z;
    const int i0 = blockIdx.y * 16;
    const int j0 = blockIdx.x * 16;

    __shared__ float4 sA[R_MAX * 32];       // 22.5 KB
    __shared__ float4 sE[R_MAX * 32];       // 22.5 KB
    __shared__ int s_psi[16], s_pei[16], s_psj[16], s_pej[16];
    __shared__ int s_meta[4];               // loA, nA(0=fallback), loE, nE

    const int tid = threadIdx.x;

    if (tid < 16) {
        s_psi[tid] = pos_s[b * SEQ + i0 + tid];
        s_pei[tid] = pos_e[b * SEQ + i0 + tid];
        s_psj[tid] = pos_s[b * SEQ + j0 + tid];
        s_pej[tid] = pos_e[b * SEQ + j0 + tid];
    }
    __syncthreads();

    if (tid == 0) {
        // sorted inputs: extrema are the endpoints
        int lo = s_psi[0]  - s_psj[15] + MAXSEQ;
        int hi = s_psi[15] - s_psj[0]  + MAXSEQ;
        int n  = hi - lo + 1;
        s_meta[0] = lo;
        s_meta[1] = (n <= R_MAX) ? n : 0;
        lo = s_pei[0]  - s_pej[15] + MAXSEQ;
        hi = s_pei[15] - s_pej[0]  + MAXSEQ;
        n  = hi - lo + 1;
        s_meta[2] = lo;
        s_meta[3] = (n <= R_MAX) ? n : 0;
    }
    __syncthreads();

    const int loA = s_meta[0], nA = s_meta[1];
    const int loE = s_meta[2], nE = s_meta[3];

    const float4* __restrict__ gA = reinterpret_cast<const float4*>(g_Ass);
    const float4* __restrict__ gE = reinterpret_cast<const float4*>(g_Aee);

    // Bulk contiguous copy of the needed row ranges (fully coalesced).
    for (int t = tid; t < nA * 32; t += 256) sA[t] = gA[loA * 32 + t];
    for (int t = tid; t < nE * 32; t += 256) sE[t] = gE[loE * 32 + t];
    __syncthreads();

    const int warp = tid >> 5;
    const int lane = tid & 31;

    // warp handles pairs p = warp*32 .. warp*32+31  ->  ii = p>>4, jj = p&15
    #pragma unroll
    for (int half = 0; half < 2; half++) {
        const int ii  = warp * 2 + half;
        const int psi = s_psi[ii];
        const int pei = s_pei[ii];
        float4* __restrict__ orow = reinterpret_cast<float4*>(out) +
            (((size_t)b * SEQ + (i0 + ii)) * SEQ + j0) * (HIDDEN / 4) + lane;

        #pragma unroll 4
        for (int jj = 0; jj < 16; jj++) {
            const int iss = psi - s_psj[jj] + MAXSEQ;   // in [1, 1023]
            const int iee = pei - s_pej[jj] + MAXSEQ;

            float4 a, e;
            if (nA) a = sA[(iss - loA) * 32 + lane];
            else    a = __ldg(gA + iss * 32 + lane);
            if (nE) e = sE[(iee - loE) * 32 + lane];
            else    e = __ldg(gE + iee * 32 + lane);

            float4 r;
            r.x = fmaxf(a.x + e.x, 0.0f);
            r.y = fmaxf(a.y + e.y, 0.0f);
            r.z = fmaxf(a.z + e.z, 0.0f);
            r.w = fmaxf(a.w + e.w, 0.0f);

            orow[jj * (HIDDEN / 4)] = r;
        }
    }
}

// ---------------------------------------------------------------------------
// Inputs (metadata order): 0 pos_s [B,S] i32, 1 pos_e [B,S] i32,
// 2 pe_ss [1025,128] f32, 3 pe_se (unused), 4 pe_es (unused),
// 5 pe_ee [1025,128] f32, 6 W [128,256] f32, 7 b [128] f32.
// Output: [B,S,S,H] f32.
// ---------------------------------------------------------------------------
extern "C" void kernel_launch(void* const* d_in, const int* in_sizes, int n_in,
                              void* d_out, int out_size)
{
    const int*   pos_s = (const int*)d_in[0];
    const int*   pos_e = (const int*)d_in[1];
    const float* pe_ss = (const float*)d_in[2];
    const float* pe_ee = (const float*)d_in[5];
    const float* W     = (const float*)d_in[6];
    const float* bias  = (const float*)d_in[7];
    float*       out   = (float*)d_out;

    dim3 grid1((TABLE_ROWS + 7) / 8, 2);
    project_tables_kernel<<<grid1, 128>>>(pe_ss, pe_ee, W, bias);

    dim3 grid2(SEQ / 16, SEQ / 16, BATCH);
    fuse_gather_tiled<<<grid2, 256>>>(pos_s, pos_e, out);
}

// round 6
// speedup vs baseline: 1.1584x; 1.0613x over previous
#include <cuda_runtime.h>
#include <cstdint>

#define TABLE_ROWS 1025
#define HIDDEN     128
#define SEQ        512
#define BATCH      2
#define MAXSEQ     512
#define R_MAX      44      // max contiguous table rows cached per table per tile

// Scratch for the projected tables (allocation-free rule: device globals).
__device__ float g_Ass[TABLE_ROWS * HIDDEN];   // pe_ss @ W[:, :128]^T + bias
__device__ float g_Aee[TABLE_ROWS * HIDDEN];   // pe_ee @ W[:, 128:]^T

// ---------------------------------------------------------------------------
// Kernel 1 (exact R1 config — measured best): project the tables.
// ---------------------------------------------------------------------------
__global__ void __launch_bounds__(128)
project_tables_kernel(const float* __restrict__ pe_ss,
                      const float* __restrict__ pe_ee,
                      const float* __restrict__ W,
                      const float* __restrict__ bias)
{
    const int sel = blockIdx.y;            // 0 -> ss, 1 -> ee
    const int t0  = blockIdx.x * 8;
    const int h   = threadIdx.x;           // 0..127

    const float* __restrict__ pe = sel ? pe_ee : pe_ss;
    float* __restrict__ outA     = sel ? g_Aee : g_Ass;

    __shared__ float pe_sm[8][HIDDEN];

    #pragma unroll
    for (int r = 0; r < 8; r++) {
        int t = t0 + r;
        pe_sm[r][h] = (t < TABLE_ROWS) ? pe[(size_t)t * HIDDEN + h] : 0.0f;
    }
    __syncthreads();

    float acc[8];
    const float binit = sel ? 0.0f : bias[h];
    #pragma unroll
    for (int r = 0; r < 8; r++) acc[r] = binit;

    const float4* __restrict__ W4 =
        reinterpret_cast<const float4*>(W + (size_t)h * (2 * HIDDEN) + sel * HIDDEN);

    #pragma unroll 8
    for (int kg = 0; kg < HIDDEN / 4; kg++) {
        const float4 w = W4[kg];
        #pragma unroll
        for (int r = 0; r < 8; r++) {
            const float4 p = reinterpret_cast<const float4*>(pe_sm[r])[kg]; // broadcast
            acc[r] += w.x * p.x + w.y * p.y + w.z * p.z + w.w * p.w;
        }
    }

    #pragma unroll
    for (int r = 0; r < 8; r++) {
        int t = t0 + r;
        if (t < TABLE_ROWS) outA[(size_t)t * HIDDEN + h] = acc[r];
    }
}

// ---------------------------------------------------------------------------
// Helpers for kernel 2
// ---------------------------------------------------------------------------
__device__ __forceinline__ void cp_async16(uint32_t saddr, const void* gaddr)
{
    asm volatile("cp.async.cg.shared.global [%0], [%1], 16;"
                 :: "r"(saddr), "l"(gaddr) : "memory");
}

// Predicated LDS.128: load only if row != prev (warp-uniform condition);
// otherwise keep the previous value that is already in the registers.
__device__ __forceinline__ void lds_if(float4& v, uint32_t saddr, int row, int prev)
{
    asm volatile(
        "{\n\t.reg .pred p;\n\t"
        "setp.ne.s32 p, %4, %5;\n\t"
        "@p ld.shared.v4.f32 {%0, %1, %2, %3}, [%6];\n\t}"
        : "+f"(v.x), "+f"(v.y), "+f"(v.z), "+f"(v.w)
        : "r"(row), "r"(prev), "r"(saddr));
}

// ---------------------------------------------------------------------------
// Kernel 2 (tiled + LDS dedup): 16x16 (i,j) tiles; the sorted positions make
// each tile's table indices a contiguous range (~33 rows), bulk-copied into
// SMEM with cp.async and served by predicated LDS (repeat indices skip the
// load). Tiles whose range exceeds R_MAX take a cold direct-__ldg path.
// grid = (32, 32, 2), block = 256 = 8 warps, warp -> 2 i-rows x 16 j.
// ---------------------------------------------------------------------------
__global__ void __launch_bounds__(256)
fuse_gather_tiled(const int* __restrict__ pos_s,
                  const int* __restrict__ pos_e,
                  float* __restrict__ out)
{
    const int b  = blockIdx.z;
    const int i0 = blockIdx.y * 16;
    const int j0 = blockIdx.x * 16;

    __shared__ float4 sA[R_MAX * 32];       // 22.5 KB
    __shared__ float4 sE[R_MAX * 32];       // 22.5 KB
    __shared__ int s_psi[16], s_pei[16], s_psj[16], s_pej[16];
    __shared__ int s_meta[4];               // loA, nA(0=fallback), loE, nE

    const int tid = threadIdx.x;

    if (tid < 16) {
        s_psi[tid] = pos_s[b * SEQ + i0 + tid];
        s_pei[tid] = pos_e[b * SEQ + i0 + tid];
        s_psj[tid] = pos_s[b * SEQ + j0 + tid];
        s_pej[tid] = pos_e[b * SEQ + j0 + tid];
    }
    __syncthreads();

    if (tid == 0) {
        int lo = s_psi[0]  - s_psj[15] + MAXSEQ;   // sorted: endpoints = extrema
        int n  = (s_psi[15] - s_psj[0] + MAXSEQ) - lo + 1;
        s_meta[0] = lo;
        s_meta[1] = (n <= R_MAX) ? n : 0;
        lo = s_pei[0]  - s_pej[15] + MAXSEQ;
        n  = (s_pei[15] - s_pej[0] + MAXSEQ) - lo + 1;
        s_meta[2] = lo;
        s_meta[3] = (n <= R_MAX) ? n : 0;
    }
    __syncthreads();

    const int loA = s_meta[0], nA = s_meta[1];
    const int loE = s_meta[2], nE = s_meta[3];

    const float4* __restrict__ gA = reinterpret_cast<const float4*>(g_Ass);
    const float4* __restrict__ gE = reinterpret_cast<const float4*>(g_Aee);

    const uint32_t sA_base = (uint32_t)__cvta_generic_to_shared(sA);
    const uint32_t sE_base = (uint32_t)__cvta_generic_to_shared(sE);

    const int warp = tid >> 5;
    const int lane = tid & 31;

    if (nA && nE) {
        // Bulk contiguous copy via cp.async (coalesced, no reg round-trip).
        for (int t = tid; t < nA * 32; t += 256)
            cp_async16(sA_base + t * 16, gA + loA * 32 + t);
        for (int t = tid; t < nE * 32; t += 256)
            cp_async16(sE_base + t * 16, gE + loE * 32 + t);
        asm volatile("cp.async.commit_group;\ncp.async.wait_group 0;" ::: "memory");
        __syncthreads();

        #pragma unroll
        for (int half = 0; half < 2; half++) {
            const int ii = warp * 2 + half;
            const int baseA = s_psi[ii] + MAXSEQ - loA;   // row = baseA - psj
            const int baseE = s_pei[ii] + MAXSEQ - loE;
            float4* __restrict__ orow = reinterpret_cast<float4*>(out) +
                (((size_t)b * SEQ + (i0 + ii)) * SEQ + j0) * (HIDDEN / 4) + lane;

            int prevA = -1, prevE = -1;
            float4 a = make_float4(0.f, 0.f, 0.f, 0.f);
            float4 e = make_float4(0.f, 0.f, 0.f, 0.f);

            #pragma unroll
            for (int jj = 0; jj < 16; jj++) {
                const int rA = baseA - s_psj[jj];         // warp-uniform
                const int rE = baseE - s_pej[jj];

                lds_if(a, sA_base + (rA * 32 + lane) * 16, rA, prevA);
                lds_if(e, sE_base + (rE * 32 + lane) * 16, rE, prevE);
                prevA = rA;
                prevE = rE;

                float4 r;
                r.x = fmaxf(a.x + e.x, 0.0f);
                r.y = fmaxf(a.y + e.y, 0.0f);
                r.z = fmaxf(a.z + e.z, 0.0f);
                r.w = fmaxf(a.w + e.w, 0.0f);

                orow[jj * (HIDDEN / 4)] = r;
            }
        }
    } else {
        // Cold path: range too wide for SMEM — direct global gathers.
        #pragma unroll
        for (int half = 0; half < 2; half++) {
            const int ii  = warp * 2 + half;
            const int psi = s_psi[ii];
            const int pei = s_pei[ii];
            float4* __restrict__ orow = reinterpret_cast<float4*>(out) +
                (((size_t)b * SEQ + (i0 + ii)) * SEQ + j0) * (HIDDEN / 4) + lane;

            for (int jj = 0; jj < 16; jj++) {
                const int iss = psi - s_psj[jj] + MAXSEQ;
                const int iee = pei - s_pej[jj] + MAXSEQ;
                const float4 a = __ldg(gA + iss * 32 + lane);
                const float4 e = __ldg(gE + iee * 32 + lane);
                float4 r;
                r.x = fmaxf(a.x + e.x, 0.0f);
                r.y = fmaxf(a.y + e.y, 0.0f);
                r.z = fmaxf(a.z + e.z, 0.0f);
                r.w = fmaxf(a.w + e.w, 0.0f);
                orow[jj * (HIDDEN / 4)] = r;
            }
        }
    }
}

// ---------------------------------------------------------------------------
// Inputs (metadata order): 0 pos_s [B,S] i32, 1 pos_e [B,S] i32,
// 2 pe_ss [1025,128] f32, 3 pe_se (unused), 4 pe_es (unused),
// 5 pe_ee [1025,128] f32, 6 W [128,256] f32, 7 b [128] f32.
// Output: [B,S,S,H] f32.
// ---------------------------------------------------------------------------
extern "C" void kernel_launch(void* const* d_in, const int* in_sizes, int n_in,
                              void* d_out, int out_size)
{
    const int*   pos_s = (const int*)d_in[0];
    const int*   pos_e = (const int*)d_in[1];
    const float* pe_ss = (const float*)d_in[2];
    const float* pe_ee = (const float*)d_in[5];
    const float* W     = (const float*)d_in[6];
    const float* bias  = (const float*)d_in[7];
    float*       out   = (float*)d_out;

    dim3 grid1((TABLE_ROWS + 7) / 8, 2);
    project_tables_kernel<<<grid1, 128>>>(pe_ss, pe_ee, W, bias);

    dim3 grid2(SEQ / 16, SEQ / 16, BATCH);
    fuse_gather_tiled<<<grid2, 256>>>(pos_s, pos_e, out);
}